// round 16
// baseline (speedup 1.0000x reference)
#include <cuda_runtime.h>
#include <cstdint>

#define Cc 256
#define Hh 56
#define Ww 56
#define XPR 80
#define XPH 58

// ---- device scratch ----
__device__ float g_xt2[8 * 8 * 58 * 58 * 36];  // [b][cich][h58][w58][ci32+pad4], tf32
__device__ float g_wB[2 * 9 * 8 * 4096];       // [mh][tap][cich][frag4096] (16co-warp order)
__device__ float g_xp[8 * 256 * XPH * XPR];    // SE path padded NCHW (borders stay 0)
__device__ float g_w1t[256 * 9 * 16];
__device__ float g_t4[4 * 8 * 16 * 56 * 56];   // conv1 ci-partials (no atomics)
__device__ float g_a[8 * 56 * 56];

__device__ __forceinline__ uint32_t smem_u32(const void* p) {
    uint32_t a;
    asm("{ .reg .u64 t; cvta.to.shared.u64 t, %1; cvt.u32.u64 %0, t; }" : "=r"(a) : "l"(p));
    return a;
}
__device__ __forceinline__ float to_tf32(float v) {
    uint32_t u;
    asm("cvt.rn.tf32.f32 %0, %1;" : "=r"(u) : "f"(v));
    return __uint_as_float(u);
}
__device__ __forceinline__ void cp16g(void* s, const void* g) {
    unsigned sa = (unsigned)__cvta_generic_to_shared(s);
    asm volatile("cp.async.cg.shared.global [%0], [%1], 16;" ::"r"(sa), "l"(g));
}
#define CP_COMMIT() asm volatile("cp.async.commit_group;")
#define CP_WAIT0() asm volatile("cp.async.wait_group 0;")

__device__ __forceinline__ void mbar_init(uint32_t a, uint32_t c) {
    asm volatile("mbarrier.init.shared::cta.b64 [%0], %1;" ::"r"(a), "r"(c) : "memory");
}
__device__ __forceinline__ void mbar_expect(uint32_t a, uint32_t tx) {
    asm volatile("mbarrier.arrive.expect_tx.shared::cta.b64 _, [%0], %1;" ::"r"(a), "r"(tx)
                 : "memory");
}
__device__ __forceinline__ void mbar_arrive(uint32_t a) {
    asm volatile("mbarrier.arrive.shared::cta.b64 _, [%0];" ::"r"(a) : "memory");
}
__device__ __forceinline__ void mbar_wait(uint32_t a, int ph) {
    asm volatile(
        "{\n\t.reg .pred P;\nW%=:\n\t"
        "mbarrier.try_wait.parity.shared::cta.b64 P, [%0], %1;\n\t"
        "@!P bra W%=;\n\t}" ::"r"(a), "r"(ph) : "memory");
}
__device__ __forceinline__ void bulk_g2s(uint32_t dst, const void* src, uint32_t bytes,
                                         uint32_t mbar) {
    asm volatile(
        "cp.async.bulk.shared::cluster.global.mbarrier::complete_tx::bytes [%0], [%1], %2, [%3];"
        ::"r"(dst), "l"(src), "r"(bytes), "r"(mbar) : "memory");
}
__device__ __forceinline__ void mma8(float* d, const uint32_t* a, uint32_t b0,
                                     uint32_t b1) {
    asm volatile(
        "mma.sync.aligned.m16n8k8.row.col.f32.tf32.tf32.f32 "
        "{%0,%1,%2,%3}, {%4,%5,%6,%7}, {%8,%9}, {%0,%1,%2,%3};"
        : "+f"(d[0]), "+f"(d[1]), "+f"(d[2]), "+f"(d[3])
        : "r"(a[0]), "r"(a[1]), "r"(a[2]), "r"(a[3]), "r"(b0), "r"(b1));
}

// ---------------------------------------------------------------------------
// prep_all (#1): grid(2, 448, 11), block(32,8).
//  z<8 : x -> g_xt2 (NHWC tf32) AND g_xp (padded NCHW)
//  z>=8: weight -> g_wB in 16co-warp m16n8k8 fragment order; se_w1 transpose.
//  Fragment e layout (4096 per [mh][tap][cich]): [mwi(8)][k8(4)][lane(32)][reg(4)]
//    row = mwi*16 + (reg&1)*8 + (lane>>2);  k = k8*8 + (reg>>1)*4 + (lane&3)
// ---------------------------------------------------------------------------
__global__ void prep_all(const float* __restrict__ x, const float* __restrict__ weight,
                         const float* __restrict__ A_w, const float* __restrict__ se_w1) {
    int z = blockIdx.z;
    int tx = threadIdx.x, ty = threadIdx.y;
    if (z < 8) {
        __shared__ float t[32][33];
        int wt = blockIdx.x, bh = blockIdx.y, cg = z;
        int b = bh / 56, h = bh % 56, w0 = wt * 32;
#pragma unroll
        for (int j = 0; j < 4; j++) {
            int ci = cg * 32 + ty + j * 8, w = w0 + tx;
            float v = 0.f;
            if (w < 56) {
                v = x[((b * 256 + ci) * 56 + h) * 56 + w];
                g_xp[((size_t)(b * 256 + ci) * XPH + h + 1) * XPR + (w + 1)] = v;
            }
            t[ty + j * 8][tx] = to_tf32(v);
        }
        __syncthreads();
#pragma unroll
        for (int j = 0; j < 4; j++) {
            int w = w0 + ty + j * 8, ci = tx;
            if (w < 56)
                g_xt2[((size_t)((b * 8 + cg) * 58 + h + 1) * 58 + (w + 1)) * 36 + ci] =
                    t[tx][ty + j * 8];
        }
    } else {
        int tid = ty * 32 + tx;
        int bid = ((z - 8) * 448 + blockIdx.y) * 2 + blockIdx.x;
        int idx = bid * 256 + tid;
        if (idx < 589824) {
            int mh = idx / 294912;
            int rest = idx % 294912;
            int tap = rest / 32768;
            int r2 = rest % 32768;
            int cich = r2 >> 12;
            int e = r2 & 4095;
            int reg = e & 3, lane = (e >> 2) & 31;
            int k8 = (e >> 7) & 3, mwi = (e >> 9) & 7;
            int gg = lane >> 2, tt = lane & 3, half = reg >> 1, s = reg & 1;
            int row = mwi * 16 + s * 8 + gg;
            int k = k8 * 8 + half * 4 + tt;
            int ci = cich * 32 + k, cog = mh * 128 + row;
            float wp = weight[cog * 2304 + ci * 9 + tap] * A_w[ci * 9 + tap];
            g_wB[((size_t)((mh * 9 + tap) * 8 + cich)) * 4096 + e] = to_tf32(wp);
        } else if (idx < 589824 + 36864) {
            int i2 = idx - 589824;
            int co = i2 & 15, tap = (i2 >> 4) % 9, ci = i2 / 144;
            g_w1t[i2] = se_w1[co * 2304 + ci * 9 + tap];
        }
    }
}

// ---------------------------------------------------------------------------
// SE conv1 (#2): ci-split x4 -> g_t4 partials. (proven)
// ---------------------------------------------------------------------------
__global__ __launch_bounds__(256) void conv_se1() {
    __shared__ __align__(16) float xs[2][6][36];
    __shared__ __align__(16) float ws[2][9][16];
    int tid = threadIdx.x, cot = tid >> 5, lane = tid & 31;
    int row = lane >> 3, col0 = (lane & 7) << 2;
    int wt = blockIdx.x, ht = blockIdx.y, z = blockIdx.z;
    int b = z >> 2, cq = z & 3;
    int h0 = ht * 4, w0 = wt * 32;
    int ci0 = cq * 64;

    bool isx = tid < 54;
    int xr = tid / 9, xc = (tid % 9) * 4;
    bool isw = (tid >= 54) && (tid < 90);
    int wi = (tid - 54) * 4;
    const float* xpb = g_xp + (long long)b * 256 * XPH * XPR;

    unsigned long long acc[4];
#pragma unroll
    for (int p = 0; p < 4; p++) acc[p] = 0ULL;

    if (isx) cp16g(&xs[0][xr][xc], xpb + (size_t)ci0 * XPH * XPR + (h0 + xr) * XPR + (w0 + xc));
    if (isw) cp16g(&ws[0][0][wi], g_w1t + ci0 * 144 + wi);
    CP_COMMIT();

    int cur = 0;
    for (int i = 0; i < 64; i++) {
        CP_WAIT0();
        __syncthreads();
        if (i + 1 < 64) {
            int nb = cur ^ 1, ci = ci0 + i + 1;
            if (isx)
                cp16g(&xs[nb][xr][xc],
                      xpb + (size_t)ci * XPH * XPR + (h0 + xr) * XPR + (w0 + xc));
            if (isw) cp16g(&ws[nb][0][wi], g_w1t + ci * 144 + wi);
            CP_COMMIT();
        }
        const float(*X)[36] = xs[cur];
        const float(*W)[16] = ws[cur];
#pragma unroll
        for (int dy = 0; dy < 3; dy++) {
            unsigned long long xd[6];
#pragma unroll
            for (int p = 0; p < 6; p++) {
                unsigned int rr = __float_as_uint(X[row + dy][col0 + p]);
                asm("mov.b64 %0, {%1, %1};" : "=l"(xd[p]) : "r"(rr));
            }
#pragma unroll
            for (int dx = 0; dx < 3; dx++) {
                unsigned long long wv = *(const unsigned long long*)&W[dy * 3 + dx][cot << 1];
#pragma unroll
                for (int p = 0; p < 4; p++)
                    asm("fma.rn.f32x2 %0, %1, %2, %0;"
                        : "+l"(acc[p]) : "l"(wv), "l"(xd[p + dx]));
            }
        }
        cur ^= 1;
    }
    int h = h0 + row, co = cot << 1;
    float* t0 = g_t4 + (size_t)cq * 401408 + ((b * 16 + co) * Hh + h) * Ww;
#pragma unroll
    for (int p = 0; p < 4; p++) {
        int w = w0 + col0 + p;
        if (w < Ww) {
            t0[w] = __uint_as_float((unsigned)acc[p]);
            t0[Hh * Ww + w] = __uint_as_float((unsigned)(acc[p] >> 32));
        }
    }
}

// ---------------------------------------------------------------------------
// SE conv2 + sigmoid (#3): sum 4 partials, relu, conv, sigmoid -> g_a.
// ---------------------------------------------------------------------------
__global__ __launch_bounds__(224) void conv_se2(const float* __restrict__ se_w2) {
    __shared__ float ws[144];
    __shared__ float ts[16][6][58];
    int tid = threadIdx.x;
    int ht = blockIdx.x, b = blockIdx.y;
    int h0 = ht * 4;
    if (tid < 144) ws[tid] = se_w2[tid];
    for (int i = tid; i < 16 * 6 * 58; i += 224) {
        int c = i % 58, r = (i / 58) % 6, ci = i / (58 * 6);
        int gh = h0 + r - 1, gw = c - 1;
        float v = 0.f;
        if (gh >= 0 && gh < Hh && gw >= 0 && gw < Ww) {
            size_t off = (size_t)((b * 16 + ci) * Hh + gh) * Ww + gw;
            float s = g_t4[off] + g_t4[401408 + off] + g_t4[2 * 401408 + off] +
                      g_t4[3 * 401408 + off];
            v = fmaxf(s, 0.f);
        }
        ts[ci][r][c] = v;
    }
    __syncthreads();
    int rr = tid / 56, w = tid % 56;
    float sum = 0.f;
#pragma unroll 1
    for (int ci = 0; ci < 16; ci++)
#pragma unroll
        for (int dy = 0; dy < 3; dy++)
#pragma unroll
            for (int dx = 0; dx < 3; dx++)
                sum += ts[ci][rr + dy][w + dx] * ws[ci * 9 + dy * 3 + dx];
    g_a[(b * Hh + h0 + rr) * Ww + w] = 1.f / (1.f + __expf(-sum));
}

// ---------------------------------------------------------------------------
// main_mma (#4, profiled): tf32 mma.sync shift-conv, 1-ROW tiles for packing.
// grid(2 mh, 56 ht, 8 b) = 896 CTAs, block 256 (8 warps, each 16co x 56n).
// 2 CTAs/SM (smem 81KB, regs ~80). B halo = 3 rows. Fused attention scale.
// ---------------------------------------------------------------------------
#define AB_BYTES 16384
#define BBF 6264                  // 3 x 58 x 36 floats
#define BB_BYTES 25056
#define A_REGION_F (2 * 4096)
#define MAIN_SMEM ((A_REGION_F + 2 * BBF) * 4)

__global__ __launch_bounds__(256, 2) void main_mma(float* __restrict__ out) {
    extern __shared__ __align__(16) float sm[];
    __shared__ __align__(8) unsigned long long mbs[8];
    uint32_t smb = smem_u32(sm);
    uint32_t mba = smem_u32(mbs);
    // fullA[0..1]@0, consA[0..1]@16, fullB[0..1]@32, consB[0..1]@48
    int tid = threadIdx.x, lane = tid & 31, wid = tid >> 5;
    int mh = blockIdx.x, h0p = blockIdx.y, b = blockIdx.z;
    int mwi = wid;  // 0..7, warp owns co [mwi*16, mwi*16+16)
    int g = lane >> 2, t = lane & 3;

    if (tid == 0) {
        for (int i = 0; i < 2; i++) mbar_init(mba + i * 8, 1);       // fullA
        for (int i = 0; i < 2; i++) mbar_init(mba + 16 + i * 8, 8);  // consA
        for (int i = 0; i < 2; i++) mbar_init(mba + 32 + i * 8, 1);  // fullB
        for (int i = 0; i < 2; i++) mbar_init(mba + 48 + i * 8, 8);  // consB
    }
    __syncthreads();

    float d[7][4];
#pragma unroll
    for (int nt = 0; nt < 7; nt++)
#pragma unroll
        for (int r = 0; r < 4; r++) d[nt][r] = 0.f;

    auto issueA = [&](int q) {
        const float* src = g_wB + (size_t)((mh * 9 + (q % 9)) * 8 + (q / 9)) * 4096;
        uint32_t mb = mba + (q & 1) * 8;
        mbar_expect(mb, AB_BYTES);
        bulk_g2s(smb + (q & 1) * AB_BYTES, src, AB_BYTES, mb);
    };
    auto issueB = [&](int c) {
        const float* src = g_xt2 + ((size_t)(b * 8 + c) * 58 + h0p) * 58 * 36;
        uint32_t mb = mba + 32 + (c & 1) * 8;
        mbar_expect(mb, BB_BYTES);
        bulk_g2s(smb + A_REGION_F * 4 + (c & 1) * BB_BYTES, src, BB_BYTES, mb);
    };

    if (tid == 0) {
        issueA(0);
        issueA(1);
        issueB(0);
    }

    int p = 0;
    for (int c = 0; c < 8; c++) {
        mbar_wait(mba + 32 + (c & 1) * 8, (c >> 1) & 1);  // fullB
        const float* Bs = sm + A_REGION_F + (c & 1) * BBF;
#pragma unroll 1
        for (int tap = 0; tap < 9; tap++, p++) {
            if (tid == 0 && tap == 0 && c + 1 < 8) {
                if (c + 1 >= 2)
                    mbar_wait(mba + 48 + ((c + 1) & 1) * 8, ((c - 1) >> 1) & 1);
                issueB(c + 1);
            }
            mbar_wait(mba + (p & 1) * 8, (p >> 1) & 1);  // fullA
            int dy = tap / 3, dx = tap % 3;
            const float4* As4 = (const float4*)(sm + (p & 1) * 4096);
            const float* pBr = Bs + (dy * 58 + g + dx) * 36 + t;
#pragma unroll
            for (int k8 = 0; k8 < 4; k8++) {
                int k0 = k8 * 8;
                float4 f = As4[(mwi * 4 + k8) * 32 + lane];
                uint32_t a[4] = {__float_as_uint(f.x), __float_as_uint(f.y),
                                 __float_as_uint(f.z), __float_as_uint(f.w)};
#pragma unroll
                for (int nt = 0; nt < 7; nt++) {
                    const float* bp = pBr + nt * 8 * 36 + k0;
                    uint32_t b0 = __float_as_uint(bp[0]);
                    uint32_t b1 = __float_as_uint(bp[4]);
                    mma8(d[nt], a, b0, b1);
                }
            }
            if (lane == 0) {
                mbar_arrive(mba + 16 + (p & 1) * 8);                // consA
                if (tap == 8) mbar_arrive(mba + 48 + (c & 1) * 8);  // consB
            }
            if (tid == 0 && p + 2 < 72) {
                mbar_wait(mba + 16 + (p & 1) * 8, (p >> 1) & 1);
                issueA(p + 2);
            }
        }
    }

    // Epilogue: fused attention scaling + store.
    // d[nt][0,1] -> co = mh*128+mwi*16+g,   cols nt*8+t*2, +1
    // d[nt][2,3] -> co+8
    const float* ga = g_a + (b * Hh + h0p) * Ww;
    int co = mh * 128 + mwi * 16 + g;
    float* ob = out + (size_t)(b * 256 + co) * 3136 + h0p * 56;
    float* ob2 = ob + 8 * 3136;
#pragma unroll
    for (int nt = 0; nt < 7; nt++) {
        int wc = nt * 8 + t * 2;
        float a0 = __ldg(ga + wc), a1 = __ldg(ga + wc + 1);
        ob[wc] = d[nt][0] * a0;
        ob[wc + 1] = d[nt][1] * a1;
        ob2[wc] = d[nt][2] * a0;
        ob2[wc + 1] = d[nt][3] * a1;
    }
}

// ---------------------------------------------------------------------------
extern "C" void kernel_launch(void* const* d_in, const int* in_sizes, int n_in,
                              void* d_out, int out_size) {
    const float* x = (const float*)d_in[0];
    const float* weight = (const float*)d_in[1];
    const float* A_w = (const float*)d_in[2];
    const float* se_w1 = (const float*)d_in[3];
    const float* se_w2 = (const float*)d_in[4];
    float* out = (float*)d_out;

    cudaFuncSetAttribute(main_mma, cudaFuncAttributeMaxDynamicSharedMemorySize, MAIN_SMEM);
    prep_all<<<dim3(2, 448, 11), dim3(32, 8)>>>(x, weight, A_w, se_w1);  // #1
    conv_se1<<<dim3(2, 14, 32), 256>>>();                                // #2
    conv_se2<<<dim3(14, 8), 224>>>(se_w2);                               // #3
    main_mma<<<dim3(2, 56, 8), 256, MAIN_SMEM>>>(out);                   // #4 (profiled)
}

// round 17
// speedup vs baseline: 1.0408x; 1.0408x over previous
#include <cuda_runtime.h>
#include <cstdint>

#define Cc 256
#define Hh 56
#define Ww 56
#define XPR 80
#define XPH 58

// ---- device scratch ----
__device__ float g_xt2[8 * 8 * 58 * 58 * 36];  // [b][cich][h58][w58][ci32+pad4], tf32
__device__ float g_wB[2 * 9 * 8 * 4096];       // [mh][tap][cich][frag4096] (32co-warp order)
__device__ float g_xp[8 * 256 * XPH * XPR];    // SE path padded NCHW (borders stay 0)
__device__ float g_w1t[256 * 9 * 16];
__device__ float g_t4[4 * 8 * 16 * 56 * 56];   // conv1 ci-partials (no atomics)
__device__ float g_a[8 * 56 * 56];
__device__ float g_o2[8 * 256 * 56 * 56];      // K-half-1 raw output

__device__ __forceinline__ uint32_t smem_u32(const void* p) {
    uint32_t a;
    asm("{ .reg .u64 t; cvta.to.shared.u64 t, %1; cvt.u32.u64 %0, t; }" : "=r"(a) : "l"(p));
    return a;
}
__device__ __forceinline__ float to_tf32(float v) {
    uint32_t u;
    asm("cvt.rn.tf32.f32 %0, %1;" : "=r"(u) : "f"(v));
    return __uint_as_float(u);
}
__device__ __forceinline__ void cp16g(void* s, const void* g) {
    unsigned sa = (unsigned)__cvta_generic_to_shared(s);
    asm volatile("cp.async.cg.shared.global [%0], [%1], 16;" ::"r"(sa), "l"(g));
}
#define CP_COMMIT() asm volatile("cp.async.commit_group;")
#define CP_WAIT0() asm volatile("cp.async.wait_group 0;")

__device__ __forceinline__ void mbar_init(uint32_t a, uint32_t c) {
    asm volatile("mbarrier.init.shared::cta.b64 [%0], %1;" ::"r"(a), "r"(c) : "memory");
}
__device__ __forceinline__ void mbar_expect(uint32_t a, uint32_t tx) {
    asm volatile("mbarrier.arrive.expect_tx.shared::cta.b64 _, [%0], %1;" ::"r"(a), "r"(tx)
                 : "memory");
}
__device__ __forceinline__ void mbar_arrive(uint32_t a) {
    asm volatile("mbarrier.arrive.shared::cta.b64 _, [%0];" ::"r"(a) : "memory");
}
__device__ __forceinline__ void mbar_wait(uint32_t a, int ph) {
    asm volatile(
        "{\n\t.reg .pred P;\nW%=:\n\t"
        "mbarrier.try_wait.parity.shared::cta.b64 P, [%0], %1;\n\t"
        "@!P bra W%=;\n\t}" ::"r"(a), "r"(ph) : "memory");
}
__device__ __forceinline__ void bulk_g2s(uint32_t dst, const void* src, uint32_t bytes,
                                         uint32_t mbar) {
    asm volatile(
        "cp.async.bulk.shared::cluster.global.mbarrier::complete_tx::bytes [%0], [%1], %2, [%3];"
        ::"r"(dst), "l"(src), "r"(bytes), "r"(mbar) : "memory");
}
__device__ __forceinline__ void mma8(float* d, const uint32_t* a, uint32_t b0,
                                     uint32_t b1) {
    asm volatile(
        "mma.sync.aligned.m16n8k8.row.col.f32.tf32.tf32.f32 "
        "{%0,%1,%2,%3}, {%4,%5,%6,%7}, {%8,%9}, {%0,%1,%2,%3};"
        : "+f"(d[0]), "+f"(d[1]), "+f"(d[2]), "+f"(d[3])
        : "r"(a[0]), "r"(a[1]), "r"(a[2]), "r"(a[3]), "r"(b0), "r"(b1));
}

// ---------------------------------------------------------------------------
// prep_all (#1): grid(2, 448, 11), block(32,8).
// Fragment e layout (R13-proven): [mwi(4)][k8(4)][mt(2)][lane(32)][reg(4)]
// ---------------------------------------------------------------------------
__global__ void prep_all(const float* __restrict__ x, const float* __restrict__ weight,
                         const float* __restrict__ A_w, const float* __restrict__ se_w1) {
    int z = blockIdx.z;
    int tx = threadIdx.x, ty = threadIdx.y;
    if (z < 8) {
        __shared__ float t[32][33];
        int wt = blockIdx.x, bh = blockIdx.y, cg = z;
        int b = bh / 56, h = bh % 56, w0 = wt * 32;
#pragma unroll
        for (int j = 0; j < 4; j++) {
            int ci = cg * 32 + ty + j * 8, w = w0 + tx;
            float v = 0.f;
            if (w < 56) {
                v = x[((b * 256 + ci) * 56 + h) * 56 + w];
                g_xp[((size_t)(b * 256 + ci) * XPH + h + 1) * XPR + (w + 1)] = v;
            }
            t[ty + j * 8][tx] = to_tf32(v);
        }
        __syncthreads();
#pragma unroll
        for (int j = 0; j < 4; j++) {
            int w = w0 + ty + j * 8, ci = tx;
            if (w < 56)
                g_xt2[((size_t)((b * 8 + cg) * 58 + h + 1) * 58 + (w + 1)) * 36 + ci] =
                    t[tx][ty + j * 8];
        }
    } else {
        int tid = ty * 32 + tx;
        int bid = ((z - 8) * 448 + blockIdx.y) * 2 + blockIdx.x;
        int idx = bid * 256 + tid;
        if (idx < 589824) {
            int mh = idx / 294912;
            int rest = idx % 294912;
            int tap = rest / 32768;
            int r2 = rest % 32768;
            int cich = r2 >> 12;
            int e = r2 & 4095;
            int reg = e & 3, lane = (e >> 2) & 31, mt = (e >> 7) & 1;
            int k8 = (e >> 8) & 3, mwi = (e >> 10) & 3;
            int gg = lane >> 2, tt = lane & 3, half = reg >> 1, s = reg & 1;
            int row = mwi * 32 + mt * 16 + s * 8 + gg;
            int k = k8 * 8 + half * 4 + tt;
            int ci = cich * 32 + k, cog = mh * 128 + row;
            float wp = weight[cog * 2304 + ci * 9 + tap] * A_w[ci * 9 + tap];
            g_wB[((size_t)((mh * 9 + tap) * 8 + cich)) * 4096 + e] = to_tf32(wp);
        } else if (idx < 589824 + 36864) {
            int i2 = idx - 589824;
            int co = i2 & 15, tap = (i2 >> 4) % 9, ci = i2 / 144;
            g_w1t[i2] = se_w1[co * 2304 + ci * 9 + tap];
        }
    }
}

// ---------------------------------------------------------------------------
// SE conv1 (#2): ci-split x4 -> g_t4 partials. (proven)
// ---------------------------------------------------------------------------
__global__ __launch_bounds__(256) void conv_se1() {
    __shared__ __align__(16) float xs[2][6][36];
    __shared__ __align__(16) float ws[2][9][16];
    int tid = threadIdx.x, cot = tid >> 5, lane = tid & 31;
    int row = lane >> 3, col0 = (lane & 7) << 2;
    int wt = blockIdx.x, ht = blockIdx.y, z = blockIdx.z;
    int b = z >> 2, cq = z & 3;
    int h0 = ht * 4, w0 = wt * 32;
    int ci0 = cq * 64;

    bool isx = tid < 54;
    int xr = tid / 9, xc = (tid % 9) * 4;
    bool isw = (tid >= 54) && (tid < 90);
    int wi = (tid - 54) * 4;
    const float* xpb = g_xp + (long long)b * 256 * XPH * XPR;

    unsigned long long acc[4];
#pragma unroll
    for (int p = 0; p < 4; p++) acc[p] = 0ULL;

    if (isx) cp16g(&xs[0][xr][xc], xpb + (size_t)ci0 * XPH * XPR + (h0 + xr) * XPR + (w0 + xc));
    if (isw) cp16g(&ws[0][0][wi], g_w1t + ci0 * 144 + wi);
    CP_COMMIT();

    int cur = 0;
    for (int i = 0; i < 64; i++) {
        CP_WAIT0();
        __syncthreads();
        if (i + 1 < 64) {
            int nb = cur ^ 1, ci = ci0 + i + 1;
            if (isx)
                cp16g(&xs[nb][xr][xc],
                      xpb + (size_t)ci * XPH * XPR + (h0 + xr) * XPR + (w0 + xc));
            if (isw) cp16g(&ws[nb][0][wi], g_w1t + ci * 144 + wi);
            CP_COMMIT();
        }
        const float(*X)[36] = xs[cur];
        const float(*W)[16] = ws[cur];
#pragma unroll
        for (int dy = 0; dy < 3; dy++) {
            unsigned long long xd[6];
#pragma unroll
            for (int p = 0; p < 6; p++) {
                unsigned int rr = __float_as_uint(X[row + dy][col0 + p]);
                asm("mov.b64 %0, {%1, %1};" : "=l"(xd[p]) : "r"(rr));
            }
#pragma unroll
            for (int dx = 0; dx < 3; dx++) {
                unsigned long long wv = *(const unsigned long long*)&W[dy * 3 + dx][cot << 1];
#pragma unroll
                for (int p = 0; p < 4; p++)
                    asm("fma.rn.f32x2 %0, %1, %2, %0;"
                        : "+l"(acc[p]) : "l"(wv), "l"(xd[p + dx]));
            }
        }
        cur ^= 1;
    }
    int h = h0 + row, co = cot << 1;
    float* t0 = g_t4 + (size_t)cq * 401408 + ((b * 16 + co) * Hh + h) * Ww;
#pragma unroll
    for (int p = 0; p < 4; p++) {
        int w = w0 + col0 + p;
        if (w < Ww) {
            t0[w] = __uint_as_float((unsigned)acc[p]);
            t0[Hh * Ww + w] = __uint_as_float((unsigned)(acc[p] >> 32));
        }
    }
}

// ---------------------------------------------------------------------------
// SE conv2 + sigmoid (#3): sum 4 partials, relu, conv, sigmoid -> g_a.
// ---------------------------------------------------------------------------
__global__ __launch_bounds__(224) void conv_se2(const float* __restrict__ se_w2) {
    __shared__ float ws[144];
    __shared__ float ts[16][6][58];
    int tid = threadIdx.x;
    int ht = blockIdx.x, b = blockIdx.y;
    int h0 = ht * 4;
    if (tid < 144) ws[tid] = se_w2[tid];
    for (int i = tid; i < 16 * 6 * 58; i += 224) {
        int c = i % 58, r = (i / 58) % 6, ci = i / (58 * 6);
        int gh = h0 + r - 1, gw = c - 1;
        float v = 0.f;
        if (gh >= 0 && gh < Hh && gw >= 0 && gw < Ww) {
            size_t off = (size_t)((b * 16 + ci) * Hh + gh) * Ww + gw;
            float s = g_t4[off] + g_t4[401408 + off] + g_t4[2 * 401408 + off] +
                      g_t4[3 * 401408 + off];
            v = fmaxf(s, 0.f);
        }
        ts[ci][r][c] = v;
    }
    __syncthreads();
    int rr = tid / 56, w = tid % 56;
    float sum = 0.f;
#pragma unroll 1
    for (int ci = 0; ci < 16; ci++)
#pragma unroll
        for (int dy = 0; dy < 3; dy++)
#pragma unroll
            for (int dx = 0; dx < 3; dx++)
                sum += ts[ci][rr + dy][w + dx] * ws[ci * 9 + dy * 3 + dx];
    g_a[(b * Hh + h0 + rr) * Ww + w] = 1.f / (1.f + __expf(-sum));
}

// ---------------------------------------------------------------------------
// main_mma (#4, profiled): tf32 mma.sync shift-conv, SPLIT-K x2.
// grid(4, 28, 8) = 896 CTAs: bx&1 = mh, bx>>1 = K-half (cich 0-3 / 4-7).
// block 256 (8 warps = 4 m x 2 rows), tile 128co x 112n, 2 CTAs/SM.
// Half 0 writes raw to out; half 1 to g_o2. Combined+scaled in scale_out.
// ---------------------------------------------------------------------------
#define AB_BYTES 16384
#define BBF 8352
#define BB_BYTES 33408
#define A_REGION_F (2 * 4096)
#define MAIN_SMEM ((A_REGION_F + 2 * BBF) * 4)
#define NCH 4   // ci-chunks per half
#define NP (9 * NCH)  // 36 A-steps per half

__global__ __launch_bounds__(256, 2) void main_mma(float* __restrict__ out) {
    extern __shared__ __align__(16) float sm[];
    __shared__ __align__(8) unsigned long long mbs[8];
    uint32_t smb = smem_u32(sm);
    uint32_t mba = smem_u32(mbs);
    int tid = threadIdx.x, lane = tid & 31, wid = tid >> 5;
    int mh = blockIdx.x & 1, kh = blockIdx.x >> 1;
    int ht = blockIdx.y, b = blockIdx.z;
    int h0p = ht * 2;
    int cbase = kh * NCH;
    int mwi = wid >> 1;
    int row = wid & 1;
    int g = lane >> 2, t = lane & 3;

    if (tid == 0) {
        for (int i = 0; i < 2; i++) mbar_init(mba + i * 8, 1);       // fullA
        for (int i = 0; i < 2; i++) mbar_init(mba + 16 + i * 8, 8);  // consA
        for (int i = 0; i < 2; i++) mbar_init(mba + 32 + i * 8, 1);  // fullB
        for (int i = 0; i < 2; i++) mbar_init(mba + 48 + i * 8, 8);  // consB
    }
    __syncthreads();

    float d[2][7][4];
#pragma unroll
    for (int mt = 0; mt < 2; mt++)
#pragma unroll
        for (int nt = 0; nt < 7; nt++)
#pragma unroll
            for (int r = 0; r < 4; r++) d[mt][nt][r] = 0.f;

    auto issueA = [&](int q) {  // q in [0,NP): tap=q%9, cich=cbase+q/9
        const float* src =
            g_wB + (size_t)((mh * 9 + (q % 9)) * 8 + cbase + (q / 9)) * 4096;
        uint32_t mb = mba + (q & 1) * 8;
        mbar_expect(mb, AB_BYTES);
        bulk_g2s(smb + (q & 1) * AB_BYTES, src, AB_BYTES, mb);
    };
    auto issueB = [&](int c) {  // c in [0,NCH)
        const float* src = g_xt2 + ((size_t)(b * 8 + cbase + c) * 58 + h0p) * 58 * 36;
        uint32_t mb = mba + 32 + (c & 1) * 8;
        mbar_expect(mb, BB_BYTES);
        bulk_g2s(smb + A_REGION_F * 4 + (c & 1) * BB_BYTES, src, BB_BYTES, mb);
    };

    if (tid == 0) {
        issueA(0);
        issueA(1);
        issueB(0);
    }

    int p = 0;
    for (int c = 0; c < NCH; c++) {
        mbar_wait(mba + 32 + (c & 1) * 8, (c >> 1) & 1);  // fullB
        const float* Bs = sm + A_REGION_F + (c & 1) * BBF;
#pragma unroll 1
        for (int tap = 0; tap < 9; tap++, p++) {
            if (tid == 0 && tap == 0 && c + 1 < NCH) {
                if (c + 1 >= 2)
                    mbar_wait(mba + 48 + ((c + 1) & 1) * 8, ((c - 1) >> 1) & 1);
                issueB(c + 1);
            }
            mbar_wait(mba + (p & 1) * 8, (p >> 1) & 1);  // fullA
            int dy = tap / 3, dx = tap % 3;
            const float4* As4 = (const float4*)(sm + (p & 1) * 4096);
            const float* pBr = Bs + ((row + dy) * 58 + g + dx) * 36 + t;
#pragma unroll
            for (int k8 = 0; k8 < 4; k8++) {
                int k0 = k8 * 8;
                float4 f0 = As4[((mwi * 4 + k8) * 2 + 0) * 32 + lane];
                float4 f1 = As4[((mwi * 4 + k8) * 2 + 1) * 32 + lane];
                uint32_t a0[4] = {__float_as_uint(f0.x), __float_as_uint(f0.y),
                                  __float_as_uint(f0.z), __float_as_uint(f0.w)};
                uint32_t a1[4] = {__float_as_uint(f1.x), __float_as_uint(f1.y),
                                  __float_as_uint(f1.z), __float_as_uint(f1.w)};
#pragma unroll
                for (int nt = 0; nt < 7; nt++) {
                    const float* bp = pBr + nt * 8 * 36 + k0;
                    uint32_t b0 = __float_as_uint(bp[0]);
                    uint32_t b1 = __float_as_uint(bp[4]);
                    mma8(d[0][nt], a0, b0, b1);
                    mma8(d[1][nt], a1, b0, b1);
                }
            }
            if (lane == 0) {
                mbar_arrive(mba + 16 + (p & 1) * 8);                // consA
                if (tap == 8) mbar_arrive(mba + 48 + (c & 1) * 8);  // consB
            }
            if (tid == 0 && p + 2 < NP) {
                mbar_wait(mba + 16 + (p & 1) * 8, (p >> 1) & 1);
                issueA(p + 2);
            }
        }
    }

    // Epilogue: RAW partial store; half 0 -> out, half 1 -> g_o2.
    float* dst = kh ? g_o2 : out;
#pragma unroll
    for (int mt = 0; mt < 2; mt++) {
        int co = mh * 128 + mwi * 32 + mt * 16 + g;
        float* ob = dst + (size_t)(b * 256 + co) * 3136;
        float* ob2 = ob + 8 * 3136;
#pragma unroll
        for (int nt = 0; nt < 7; nt++) {
            int off = (h0p + row) * 56 + nt * 8 + t * 2;
            ob[off] = d[mt][nt][0];
            ob[off + 1] = d[mt][nt][1];
            ob2[off] = d[mt][nt][2];
            ob2[off + 1] = d[mt][nt][3];
        }
    }
}

// scale_out (#5): out = (out + g_o2) * a, float4 over 8*256*784 elements.
__global__ __launch_bounds__(256) void scale_out(float* __restrict__ out) {
    int idx = blockIdx.x * 256 + threadIdx.x;
    if (idx >= 8 * 256 * 784) return;
    int hw4 = idx % 784;
    int b = idx / (784 * 256);
    float4 v = ((float4*)out)[idx];
    const float4 u = ((const float4*)g_o2)[idx];
    const float4 a = ((const float4*)g_a)[b * 784 + hw4];
    v.x = (v.x + u.x) * a.x;
    v.y = (v.y + u.y) * a.y;
    v.z = (v.z + u.z) * a.z;
    v.w = (v.w + u.w) * a.w;
    ((float4*)out)[idx] = v;
}

// ---------------------------------------------------------------------------
extern "C" void kernel_launch(void* const* d_in, const int* in_sizes, int n_in,
                              void* d_out, int out_size) {
    const float* x = (const float*)d_in[0];
    const float* weight = (const float*)d_in[1];
    const float* A_w = (const float*)d_in[2];
    const float* se_w1 = (const float*)d_in[3];
    const float* se_w2 = (const float*)d_in[4];
    float* out = (float*)d_out;

    cudaFuncSetAttribute(main_mma, cudaFuncAttributeMaxDynamicSharedMemorySize, MAIN_SMEM);
    prep_all<<<dim3(2, 448, 11), dim3(32, 8)>>>(x, weight, A_w, se_w1);  // #1
    conv_se1<<<dim3(2, 14, 32), 256>>>();                                // #2
    conv_se2<<<dim3(14, 8), 224>>>(se_w2);                               // #3
    main_mma<<<dim3(4, 28, 8), 256, MAIN_SMEM>>>(out);                   // #4 (profiled)
    scale_out<<<(8 * 256 * 784 + 255) / 256, 256>>>(out);                // #5
}